// round 8
// baseline (speedup 1.0000x reference)
#include <cuda_runtime.h>
#include <cuda_bf16.h>
#include <math.h>

#define BATCH 8
#define DIM 96
#define HH 192
#define WW 192
#define NEXP 6
#define TOPK 3

typedef unsigned long long u64;

// ---------- packed f32x2 helpers (sm_103a) ----------
__device__ __forceinline__ u64 pk2(float lo, float hi) {
    u64 d; asm("mov.b64 %0, {%1, %2};" : "=l"(d) : "f"(lo), "f"(hi)); return d;
}
__device__ __forceinline__ void upk2(u64 d, float& lo, float& hi) {
    asm("mov.b64 {%0, %1}, %2;" : "=f"(lo), "=f"(hi) : "l"(d));
}
__device__ __forceinline__ u64 fma2(u64 a, u64 b, u64 c) {
    u64 d; asm("fma.rn.f32x2 %0, %1, %2, %3;" : "=l"(d) : "l"(a), "l"(b), "l"(c)); return d;
}
__device__ __forceinline__ u64 add2(u64 a, u64 b) {
    u64 d; asm("add.rn.f32x2 %0, %1, %2;" : "=l"(d) : "l"(a), "l"(b)); return d;
}
// per-group named barrier: 96 threads (3 warps), barrier id = group
__device__ __forceinline__ void barg(int g) {
    asm volatile("bar.sync %0, 96;" :: "r"(g) : "memory");
}

// ---------- device scratch ----------
__device__ float g_pooled[BATCH * DIM];
__device__ int   g_idx[BATCH * TOPK];
__device__ float g_w[BATCH * TOPK];

// ---------------------------------------------------------------
// Kernel A: per-(b,c) max+mean pooling over HxW
// ---------------------------------------------------------------
__global__ __launch_bounds__(256) void pool_kernel(const float* __restrict__ x) {
    int bc = blockIdx.x;
    const float4* p4 = reinterpret_cast<const float4*>(x + (size_t)bc * (HH * WW));
    float mx = -1e30f, sm = 0.f;
    for (int i = threadIdx.x; i < (HH * WW / 4); i += 256) {
        float4 v = p4[i];
        mx = fmaxf(mx, fmaxf(fmaxf(v.x, v.y), fmaxf(v.z, v.w)));
        sm += (v.x + v.y) + (v.z + v.w);
    }
#pragma unroll
    for (int o = 16; o; o >>= 1) {
        mx = fmaxf(mx, __shfl_xor_sync(0xffffffffu, mx, o));
        sm += __shfl_xor_sync(0xffffffffu, sm, o);
    }
    __shared__ float smx[8], ssm[8];
    int w = threadIdx.x >> 5, l = threadIdx.x & 31;
    if (l == 0) { smx[w] = mx; ssm[w] = sm; }
    __syncthreads();
    if (threadIdx.x == 0) {
        float M = smx[0], S = ssm[0];
#pragma unroll
        for (int i = 1; i < 8; i++) { M = fmaxf(M, smx[i]); S += ssm[i]; }
        g_pooled[bc] = M + S * (1.0f / (HH * WW));
    }
}

// ---------------------------------------------------------------
// Kernel B: gate
// ---------------------------------------------------------------
__global__ __launch_bounds__(64) void gate_kernel(const float* __restrict__ w_fc0,
                                                  const float* __restrict__ b_fc0,
                                                  const float* __restrict__ w_fc1,
                                                  const float* __restrict__ b_fc1) {
    __shared__ float sh_g[BATCH][NEXP], sh_nz[BATCH][NEXP];
    int t = threadIdx.x;
    if (t < BATCH * NEXP) {
        int b = t / NEXP, e = t - b * NEXP;
        const float* p = g_pooled + b * DIM;
        float d0 = b_fc0[e], d1 = b_fc1[e];
        for (int c = 0; c < DIM; c++) {
            float pv = p[c];
            d0 = fmaf(pv, w_fc0[e * DIM + c], d0);
            d1 = fmaf(pv, w_fc1[e * DIM + c], d1);
        }
        sh_g[b][e]  = (d1 >= 0.f) ? d1 : 0.2f * d1;
        sh_nz[b][e] = fmaxf(d0, 0.f) + log1pf(expf(-fabsf(d0)));
    }
    __syncthreads();
    if (t < BATCH) {
        int b = t;
        float g[NEXP], nz[NEXP];
#pragma unroll
        for (int e = 0; e < NEXP; e++) { g[e] = sh_g[b][e]; nz[e] = sh_nz[b][e]; }
        float mu = 0.f;
#pragma unroll
        for (int e = 0; e < NEXP; e++) mu += nz[e];
        mu *= (1.0f / NEXP);
        float var = 0.f;
#pragma unroll
        for (int e = 0; e < NEXP; e++) { float d = nz[e] - mu; var += d * d; }
        float sd = sqrtf(var / (NEXP - 1));
        float sc[NEXP];
#pragma unroll
        for (int e = 0; e < NEXP; e++) sc[e] = g[e] + (nz[e] - mu) / sd;

        bool used[NEXP] = {false, false, false, false, false, false};
        int idx[TOPK];
#pragma unroll
        for (int k = 0; k < TOPK; k++) {
            float best = -1e30f; int bi = 0;
#pragma unroll
            for (int e = 0; e < NEXP; e++)
                if (!used[e] && sc[e] > best) { best = sc[e]; bi = e; }
            used[bi] = true;
            idx[k] = bi;
        }
        float m = fmaxf(g[idx[0]], fmaxf(g[idx[1]], g[idx[2]]));
        float ex[TOPK], s = 0.f;
#pragma unroll
        for (int k = 0; k < TOPK; k++) { ex[k] = expf(g[idx[k]] - m); s += ex[k]; }
        float inv = 1.0f / s;
#pragma unroll
        for (int k = 0; k < TOPK; k++) {
            g_idx[b * TOPK + k] = idx[k];
            g_w[b * TOPK + k]   = ex[k] * inv;
        }
    }
}

// ---------------------------------------------------------------
// Kernel C: fused conv1 -> relu -> conv2 -> weighted sum (f32x2).
// 384 threads = 4 independent 96-thread groups (12 warps -> 3 per SMSP,
// perfectly balanced). Group g handles 16-row tile (4*bx + g) with its own
// smem region and its own named barrier. Inner code identical to the
// 168us R4 kernel.
// ---------------------------------------------------------------
#define INW 196
#define INW2 98
#define GROUP_F (20 * INW + 18 * INW)   // in_s + c1_s floats per group
#define MOE_SMEM_BYTES (4 * GROUP_F * 4)

struct P3 { u64 p0, p1, p2; };

__device__ __forceinline__ P3 load3(const float2* row, int t) {
    float2 L = row[t];       // idx (2t, 2t+1)   = cols (2t-1, 2t)
    float2 R = row[t + 1];   // idx (2t+2, 2t+3) = cols (2t+1, 2t+2)
    P3 r;
    r.p0 = pk2(L.x, L.y);
    r.p1 = pk2(L.y, R.x);
    r.p2 = pk2(R.x, R.y);
    return r;
}

__global__ __launch_bounds__(384) void moe_kernel(
    const float* __restrict__ x,
    const float* __restrict__ ew1, const float* __restrict__ eb1,
    const float* __restrict__ ew2, const float* __restrict__ eb2,
    float* __restrict__ out)
{
    extern __shared__ __align__(16) float smem[];
    const int tid = threadIdx.x;
    const int g   = tid / 96;               // group 0..3
    const int t   = tid - g * 96;           // 0..95, column pair (2t, 2t+1)
    const int h0  = (blockIdx.x * 4 + g) * 16;
    const int c   = blockIdx.y;
    const int b   = blockIdx.z;

    // per-group smem: x tile rows h0-2..h0+17 (20), col j at idx j+1;
    //                 c1 tile rows h0-1..h0+16 (18), col j at idx j+1.
    float* in_s = smem + g * GROUP_F;
    float* c1_s = in_s + 20 * INW;

    const float* xp = x + (size_t)(b * DIM + c) * (HH * WW);
    for (int idx = t; idx < 20 * INW; idx += 96) {
        int ri = idx / INW, ji = idx - ri * INW;
        int h = h0 - 2 + ri, w = ji - 1;
        float v = 0.f;
        if ((unsigned)h < (unsigned)HH && (unsigned)w < (unsigned)WW)
            v = xp[h * WW + w];
        in_s[idx] = v;
    }
    // c1 halo columns (col -1 at idx 0, col 192 at idx 193) are always zero
    if (t < 18) { c1_s[t * INW + 0] = 0.f; c1_s[t * INW + 193] = 0.f; }

    u64 acc[16];
#pragma unroll
    for (int r = 0; r < 16; r++) acc[r] = 0ull;
    barg(g);

    const float2* in2 = reinterpret_cast<const float2*>(in_s);
    const float2* c12 = reinterpret_cast<const float2*>(c1_s);

    for (int ki = 0; ki < TOPK; ki++) {
        const int   e   = g_idx[b * TOPK + ki];
        const float cof = g_w[b * TOPK + ki];
        const float* w1 = ew1 + ((size_t)e * DIM + c) * 9;
        const float* w2 = ew2 + ((size_t)e * DIM + c) * 9;

        // ---- conv1 + relu -> c1_s ----
        {
            u64 K0 = pk2(w1[0], w1[0]), K1 = pk2(w1[1], w1[1]), K2 = pk2(w1[2], w1[2]);
            u64 K3 = pk2(w1[3], w1[3]), K4 = pk2(w1[4], w1[4]), K5 = pk2(w1[5], w1[5]);
            u64 K6 = pk2(w1[6], w1[6]), K7 = pk2(w1[7], w1[7]), K8 = pk2(w1[8], w1[8]);
            float b1v = eb1[e * DIM + c];
            u64 B1 = pk2(b1v, b1v);

            P3 A = load3(in2 + 0 * INW2, t);
            P3 B = load3(in2 + 1 * INW2, t);
#pragma unroll
            for (int r = 0; r < 18; r++) {
                P3 C = load3(in2 + (r + 2) * INW2, t);
                u64 v = fma2(K0, A.p0, fma2(K1, A.p1, fma2(K2, A.p2,
                        fma2(K3, B.p0, fma2(K4, B.p1, fma2(K5, B.p2,
                        fma2(K6, C.p0, fma2(K7, C.p1, fma2(K8, C.p2, B1)))))))));
                float v0, v1; upk2(v, v0, v1);
                const int hr = h0 + r - 1;
                const bool hok = (unsigned)hr < (unsigned)HH;
                // conv2's zero padding lives in the conv1-output domain
                c1_s[r * INW + 2 * t + 1] = hok ? fmaxf(v0, 0.f) : 0.f;
                c1_s[r * INW + 2 * t + 2] = hok ? fmaxf(v1, 0.f) : 0.f;
                A = B; B = C;
            }
        }
        barg(g);

        // ---- conv2 (weights pre-scaled by gate coeff), accumulate ----
        {
            u64 S0 = pk2(cof * w2[0], cof * w2[0]), S1 = pk2(cof * w2[1], cof * w2[1]);
            u64 S2 = pk2(cof * w2[2], cof * w2[2]), S3 = pk2(cof * w2[3], cof * w2[3]);
            u64 S4 = pk2(cof * w2[4], cof * w2[4]), S5 = pk2(cof * w2[5], cof * w2[5]);
            u64 S6 = pk2(cof * w2[6], cof * w2[6]), S7 = pk2(cof * w2[7], cof * w2[7]);
            u64 S8 = pk2(cof * w2[8], cof * w2[8]);
            float bbv = cof * eb2[e * DIM + c];
            u64 BB = pk2(bbv, bbv);

            P3 A = load3(c12 + 0 * INW2, t);
            P3 B = load3(c12 + 1 * INW2, t);
#pragma unroll
            for (int r = 0; r < 16; r++) {
                P3 C = load3(c12 + (r + 2) * INW2, t);
                acc[r] = fma2(S0, A.p0, fma2(S1, A.p1, fma2(S2, A.p2,
                         fma2(S3, B.p0, fma2(S4, B.p1, fma2(S5, B.p2,
                         fma2(S6, C.p0, fma2(S7, C.p1, fma2(S8, C.p2,
                         add2(acc[r], BB))))))))));
                A = B; B = C;
            }
        }
        barg(g);
    }

    float* op = out + (size_t)(b * DIM + c) * (HH * WW) + h0 * WW + 2 * t;
#pragma unroll
    for (int r = 0; r < 16; r++) {
        float o0, o1; upk2(acc[r], o0, o1);
        reinterpret_cast<float2*>(op + r * WW)[0] = make_float2(o0, o1);
    }
}

// ---------------------------------------------------------------
extern "C" void kernel_launch(void* const* d_in, const int* in_sizes, int n_in,
                              void* d_out, int out_size) {
    const float* x     = (const float*)d_in[0];
    const float* w_fc0 = (const float*)d_in[1];
    const float* b_fc0 = (const float*)d_in[2];
    const float* w_fc1 = (const float*)d_in[3];
    const float* b_fc1 = (const float*)d_in[4];
    const float* ew1   = (const float*)d_in[5];
    const float* eb1   = (const float*)d_in[6];
    const float* ew2   = (const float*)d_in[7];
    const float* eb2   = (const float*)d_in[8];
    float* out = (float*)d_out;

    cudaFuncSetAttribute(moe_kernel,
                         cudaFuncAttributeMaxDynamicSharedMemorySize,
                         MOE_SMEM_BYTES);

    pool_kernel<<<BATCH * DIM, 256>>>(x);
    gate_kernel<<<1, 64>>>(w_fc0, b_fc0, w_fc1, b_fc1);
    dim3 grid(HH / 64, DIM, BATCH);   // 4 tiles per block (one per group)
    moe_kernel<<<grid, 384, MOE_SMEM_BYTES>>>(x, ew1, eb1, ew2, eb2, out);
}

// round 9
// speedup vs baseline: 1.2633x; 1.2633x over previous
#include <cuda_runtime.h>
#include <cuda_bf16.h>
#include <math.h>

#define BATCH 8
#define DIM 96
#define HH 192
#define WW 192
#define NEXP 6
#define TOPK 3

typedef unsigned long long u64;

// ---------- packed f32x2 helpers (sm_103a) ----------
__device__ __forceinline__ u64 pk2(float lo, float hi) {
    u64 d; asm("mov.b64 %0, {%1, %2};" : "=l"(d) : "f"(lo), "f"(hi)); return d;
}
__device__ __forceinline__ void upk2(u64 d, float& lo, float& hi) {
    asm("mov.b64 {%0, %1}, %2;" : "=f"(lo), "=f"(hi) : "l"(d));
}
__device__ __forceinline__ u64 fma2(u64 a, u64 b, u64 c) {
    u64 d; asm("fma.rn.f32x2 %0, %1, %2, %3;" : "=l"(d) : "l"(a), "l"(b), "l"(c)); return d;
}
__device__ __forceinline__ u64 add2(u64 a, u64 b) {
    u64 d; asm("add.rn.f32x2 %0, %1, %2;" : "=l"(d) : "l"(a), "l"(b)); return d;
}

// ---------- device scratch ----------
__device__ float g_pooled[BATCH * DIM];
__device__ int   g_idx[BATCH * TOPK];
__device__ float g_w[BATCH * TOPK];

// ---------------------------------------------------------------
// Kernel A: per-(b,c) max+mean pooling over HxW
// ---------------------------------------------------------------
__global__ __launch_bounds__(256) void pool_kernel(const float* __restrict__ x) {
    int bc = blockIdx.x;
    const float4* p4 = reinterpret_cast<const float4*>(x + (size_t)bc * (HH * WW));
    float mx = -1e30f, sm = 0.f;
    for (int i = threadIdx.x; i < (HH * WW / 4); i += 256) {
        float4 v = p4[i];
        mx = fmaxf(mx, fmaxf(fmaxf(v.x, v.y), fmaxf(v.z, v.w)));
        sm += (v.x + v.y) + (v.z + v.w);
    }
#pragma unroll
    for (int o = 16; o; o >>= 1) {
        mx = fmaxf(mx, __shfl_xor_sync(0xffffffffu, mx, o));
        sm += __shfl_xor_sync(0xffffffffu, sm, o);
    }
    __shared__ float smx[8], ssm[8];
    int w = threadIdx.x >> 5, l = threadIdx.x & 31;
    if (l == 0) { smx[w] = mx; ssm[w] = sm; }
    __syncthreads();
    if (threadIdx.x == 0) {
        float M = smx[0], S = ssm[0];
#pragma unroll
        for (int i = 1; i < 8; i++) { M = fmaxf(M, smx[i]); S += ssm[i]; }
        g_pooled[bc] = M + S * (1.0f / (HH * WW));
    }
}

// ---------------------------------------------------------------
// Kernel B: gate
// ---------------------------------------------------------------
__global__ __launch_bounds__(64) void gate_kernel(const float* __restrict__ w_fc0,
                                                  const float* __restrict__ b_fc0,
                                                  const float* __restrict__ w_fc1,
                                                  const float* __restrict__ b_fc1) {
    __shared__ float sh_g[BATCH][NEXP], sh_nz[BATCH][NEXP];
    int t = threadIdx.x;
    if (t < BATCH * NEXP) {
        int b = t / NEXP, e = t - b * NEXP;
        const float* p = g_pooled + b * DIM;
        float d0 = b_fc0[e], d1 = b_fc1[e];
        for (int c = 0; c < DIM; c++) {
            float pv = p[c];
            d0 = fmaf(pv, w_fc0[e * DIM + c], d0);
            d1 = fmaf(pv, w_fc1[e * DIM + c], d1);
        }
        sh_g[b][e]  = (d1 >= 0.f) ? d1 : 0.2f * d1;
        sh_nz[b][e] = fmaxf(d0, 0.f) + log1pf(expf(-fabsf(d0)));
    }
    __syncthreads();
    if (t < BATCH) {
        int b = t;
        float g[NEXP], nz[NEXP];
#pragma unroll
        for (int e = 0; e < NEXP; e++) { g[e] = sh_g[b][e]; nz[e] = sh_nz[b][e]; }
        float mu = 0.f;
#pragma unroll
        for (int e = 0; e < NEXP; e++) mu += nz[e];
        mu *= (1.0f / NEXP);
        float var = 0.f;
#pragma unroll
        for (int e = 0; e < NEXP; e++) { float d = nz[e] - mu; var += d * d; }
        float sd = sqrtf(var / (NEXP - 1));
        float sc[NEXP];
#pragma unroll
        for (int e = 0; e < NEXP; e++) sc[e] = g[e] + (nz[e] - mu) / sd;

        bool used[NEXP] = {false, false, false, false, false, false};
        int idx[TOPK];
#pragma unroll
        for (int k = 0; k < TOPK; k++) {
            float best = -1e30f; int bi = 0;
#pragma unroll
            for (int e = 0; e < NEXP; e++)
                if (!used[e] && sc[e] > best) { best = sc[e]; bi = e; }
            used[bi] = true;
            idx[k] = bi;
        }
        float m = fmaxf(g[idx[0]], fmaxf(g[idx[1]], g[idx[2]]));
        float ex[TOPK], s = 0.f;
#pragma unroll
        for (int k = 0; k < TOPK; k++) { ex[k] = expf(g[idx[k]] - m); s += ex[k]; }
        float inv = 1.0f / s;
#pragma unroll
        for (int k = 0; k < TOPK; k++) {
            g_idx[b * TOPK + k] = idx[k];
            g_w[b * TOPK + k]   = ex[k] * inv;
        }
    }
}

// ---------------------------------------------------------------
// Kernel C: fused conv1 -> relu -> conv2 -> weighted sum (f32x2).
// 96 threads; thread t owns column pair (2t, 2t+1) for a 16-row tile.
// conv1 results live in REGISTERS (18 packed rows/thread); conv2 gets
// neighbor columns via warp shuffles; the 2 floats/row crossing each warp
// boundary go through a tiny parity-buffered smem edge array (1 bar/expert).
// Both convs are in scatter form (source row -> up to 3 dest rows).
// ---------------------------------------------------------------
#define INW 196
#define INW2 98

struct P3 { u64 p0, p1, p2; };

// input window from in_s (col j at float idx j+1): 2 aligned LDS.64
__device__ __forceinline__ P3 load3(const float2* row, int t) {
    float2 L = row[t];       // cols (2t-1, 2t)
    float2 R = row[t + 1];   // cols (2t+1, 2t+2)
    P3 r;
    r.p0 = pk2(L.x, L.y);
    r.p1 = pk2(L.y, R.x);
    r.p2 = pk2(R.x, R.y);
    return r;
}

__global__ __launch_bounds__(96) void moe_kernel(
    const float* __restrict__ x,
    const float* __restrict__ ew1, const float* __restrict__ eb1,
    const float* __restrict__ ew2, const float* __restrict__ eb2,
    float* __restrict__ out)
{
    const int t    = threadIdx.x;            // 0..95, column pair (2t, 2t+1)
    const int w    = t >> 5;                 // warp 0..2
    const int lane = t & 31;
    const int h0   = blockIdx.x * 16;
    const int c    = blockIdx.y;
    const int b    = blockIdx.z;

    // x tile: rows h0-2..h0+17 (20), col j at idx j+1; idx 0 & 193 zero pad
    __shared__ __align__(16) float in_s[20 * INW];
    // warp-boundary exchange: c1 col (64w-1) for warp w (edge_L) and
    // c1 col (64w+64) for warp w (edge_R); parity-buffered per expert.
    __shared__ float edge_L[2][3][18];
    __shared__ float edge_R[2][3][18];

    const float* xp = x + (size_t)(b * DIM + c) * (HH * WW);
    for (int idx = t; idx < 20 * INW; idx += 96) {
        int ri = idx / INW, ji = idx - ri * INW;
        int h = h0 - 2 + ri, wc = ji - 1;
        float v = 0.f;
        if ((unsigned)h < (unsigned)HH && (unsigned)wc < (unsigned)WW)
            v = xp[h * WW + wc];
        in_s[idx] = v;
    }
    // constant-zero edge slots (image W borders): warp0 left, warp2 right
    if (t < 18) {
        edge_L[0][0][t] = 0.f; edge_L[1][0][t] = 0.f;
        edge_R[0][2][t] = 0.f; edge_R[1][2][t] = 0.f;
    }

    u64 acc[16];
#pragma unroll
    for (int r = 0; r < 16; r++) acc[r] = 0ull;
    __syncthreads();

    const float2* in2 = reinterpret_cast<const float2*>(in_s);
    const bool is_l0  = (lane == 0);
    const bool is_l31 = (lane == 31);

    u64 c1r[18];   // packed relu(conv1) rows, register-resident

    for (int ki = 0; ki < TOPK; ki++) {
        const int   e   = g_idx[b * TOPK + ki];
        const float cof = g_w[b * TOPK + ki];
        const float* w1 = ew1 + ((size_t)e * DIM + c) * 9;
        const float* w2 = ew2 + ((size_t)e * DIM + c) * 9;
        const int p = ki & 1;

        // ---- conv1 (scatter: in_s row ri -> c1 rows ri, ri-1, ri-2) ----
        {
            const u64 K0 = pk2(w1[0], w1[0]), K1 = pk2(w1[1], w1[1]), K2 = pk2(w1[2], w1[2]);
            const u64 K3 = pk2(w1[3], w1[3]), K4 = pk2(w1[4], w1[4]), K5 = pk2(w1[5], w1[5]);
            const u64 K6 = pk2(w1[6], w1[6]), K7 = pk2(w1[7], w1[7]), K8 = pk2(w1[8], w1[8]);
            const float b1v = eb1[e * DIM + c];
            const u64 B1 = pk2(b1v, b1v);
#pragma unroll
            for (int rr = 0; rr < 18; rr++) c1r[rr] = B1;
#pragma unroll
            for (int ri = 0; ri < 20; ri++) {
                P3 X = load3(in2 + ri * INW2, t);
                if (ri <= 17)               // top taps of c1 row ri
                    c1r[ri]     = fma2(K0, X.p0, fma2(K1, X.p1, fma2(K2, X.p2, c1r[ri])));
                if (ri >= 1 && ri <= 18)    // middle taps of c1 row ri-1
                    c1r[ri - 1] = fma2(K3, X.p0, fma2(K4, X.p1, fma2(K5, X.p2, c1r[ri - 1])));
                if (ri >= 2)                // bottom taps of c1 row ri-2
                    c1r[ri - 2] = fma2(K6, X.p0, fma2(K7, X.p1, fma2(K8, X.p2, c1r[ri - 2])));
            }
            // relu + row mask (conv2 zero-pad lives in conv1-output domain) + edge export
#pragma unroll
            for (int rr = 0; rr < 18; rr++) {
                float v0, v1; upk2(c1r[rr], v0, v1);
                const int hr = h0 + rr - 1;
                const bool hok = (unsigned)hr < (unsigned)HH;
                float r0 = hok ? fmaxf(v0, 0.f) : 0.f;
                float r1 = hok ? fmaxf(v1, 0.f) : 0.f;
                c1r[rr] = pk2(r0, r1);
                if (is_l31 && w < 2) edge_L[p][w + 1][rr] = r1;  // col 64w+63
                if (is_l0  && w > 0) edge_R[p][w - 1][rr] = r0;  // col 64w
            }
        }
        __syncthreads();

        // ---- conv2 (scatter: c1 row rr -> acc rows rr, rr-1, rr-2) ----
        {
            const u64 S0 = pk2(cof * w2[0], cof * w2[0]), S1 = pk2(cof * w2[1], cof * w2[1]);
            const u64 S2 = pk2(cof * w2[2], cof * w2[2]), S3 = pk2(cof * w2[3], cof * w2[3]);
            const u64 S4 = pk2(cof * w2[4], cof * w2[4]), S5 = pk2(cof * w2[5], cof * w2[5]);
            const u64 S6 = pk2(cof * w2[6], cof * w2[6]), S7 = pk2(cof * w2[7], cof * w2[7]);
            const u64 S8 = pk2(cof * w2[8], cof * w2[8]);
            const float bbv = cof * eb2[e * DIM + c];
            const u64 BB = pk2(bbv, bbv);
#pragma unroll
            for (int rr = 0; rr < 18; rr++) {
                float lo, hi; upk2(c1r[rr], lo, hi);
                float lft = __shfl_up_sync(0xffffffffu, hi, 1);   // col 2t-1
                float rgt = __shfl_down_sync(0xffffffffu, lo, 1); // col 2t+2
                float lv = edge_L[p][w][rr];
                float rv = edge_R[p][w][rr];
                if (is_l0)  lft = lv;
                if (is_l31) rgt = rv;
                u64 p0 = pk2(lft, lo);
                u64 p1 = c1r[rr];
                u64 p2 = pk2(hi, rgt);
                if (rr <= 15)               // c1 row rr is TOP row of output rr
                    acc[rr]     = fma2(S0, p0, fma2(S1, p1, fma2(S2, p2, acc[rr])));
                if (rr >= 1 && rr <= 16)    // middle of output rr-1
                    acc[rr - 1] = fma2(S3, p0, fma2(S4, p1, fma2(S5, p2, acc[rr - 1])));
                if (rr >= 2)                // bottom of output rr-2
                    acc[rr - 2] = fma2(S6, p0, fma2(S7, p1, fma2(S8, p2, acc[rr - 2])));
            }
#pragma unroll
            for (int o = 0; o < 16; o++) acc[o] = add2(acc[o], BB);
        }
        // no barrier needed here: next expert writes parity p^1, and block-wide
        // bars after its conv1 order everything before parity p is reused.
    }

    float* op = out + (size_t)(b * DIM + c) * (HH * WW) + h0 * WW + 2 * t;
#pragma unroll
    for (int r = 0; r < 16; r++) {
        float o0, o1; upk2(acc[r], o0, o1);
        reinterpret_cast<float2*>(op + r * WW)[0] = make_float2(o0, o1);
    }
}

// ---------------------------------------------------------------
extern "C" void kernel_launch(void* const* d_in, const int* in_sizes, int n_in,
                              void* d_out, int out_size) {
    const float* x     = (const float*)d_in[0];
    const float* w_fc0 = (const float*)d_in[1];
    const float* b_fc0 = (const float*)d_in[2];
    const float* w_fc1 = (const float*)d_in[3];
    const float* b_fc1 = (const float*)d_in[4];
    const float* ew1   = (const float*)d_in[5];
    const float* eb1   = (const float*)d_in[6];
    const float* ew2   = (const float*)d_in[7];
    const float* eb2   = (const float*)d_in[8];
    float* out = (float*)d_out;

    pool_kernel<<<BATCH * DIM, 256>>>(x);
    gate_kernel<<<1, 64>>>(w_fc0, b_fc0, w_fc1, b_fc1);
    dim3 grid(HH / 16, DIM, BATCH);
    moe_kernel<<<grid, 96>>>(x, ew1, eb1, ew2, eb2, out);
}

// round 10
// speedup vs baseline: 1.3602x; 1.0767x over previous
#include <cuda_runtime.h>
#include <cuda_bf16.h>
#include <math.h>

#define BATCH 8
#define DIM 96
#define HH 192
#define WW 192
#define NEXP 6
#define TOPK 3

typedef unsigned long long u64;

// ---------- packed f32x2 helpers (sm_103a) ----------
__device__ __forceinline__ u64 pk2(float lo, float hi) {
    u64 d; asm("mov.b64 %0, {%1, %2};" : "=l"(d) : "f"(lo), "f"(hi)); return d;
}
__device__ __forceinline__ void upk2(u64 d, float& lo, float& hi) {
    asm("mov.b64 {%0, %1}, %2;" : "=f"(lo), "=f"(hi) : "l"(d));
}
__device__ __forceinline__ u64 fma2(u64 a, u64 b, u64 c) {
    u64 d; asm("fma.rn.f32x2 %0, %1, %2, %3;" : "=l"(d) : "l"(a), "l"(b), "l"(c)); return d;
}
__device__ __forceinline__ u64 add2(u64 a, u64 b) {
    u64 d; asm("add.rn.f32x2 %0, %1, %2;" : "=l"(d) : "l"(a), "l"(b)); return d;
}

// ---------- device scratch ----------
__device__ float g_pooled[BATCH * DIM];
__device__ int   g_idx[BATCH * TOPK];
__device__ float g_w[BATCH * TOPK];
__device__ unsigned int g_done = 0;   // self-resetting completion counter

// ---------------------------------------------------------------
// Kernel A: fused pooling + gate.
// 768 blocks do per-(b,c) max+mean pooling; the LAST block to finish
// additionally computes the gate (top-3 routing) for all batches.
// Counter self-resets to 0 so every graph replay behaves identically.
// ---------------------------------------------------------------
__global__ __launch_bounds__(256) void pool_gate_kernel(
    const float* __restrict__ x,
    const float* __restrict__ w_fc0, const float* __restrict__ b_fc0,
    const float* __restrict__ w_fc1, const float* __restrict__ b_fc1)
{
    __shared__ float smx[8], ssm[8];
    __shared__ int   s_last;
    __shared__ float sh_g[BATCH][NEXP], sh_nz[BATCH][NEXP];

    const int bc = blockIdx.x;
    const int tid = threadIdx.x;
    const float4* p4 = reinterpret_cast<const float4*>(x + (size_t)bc * (HH * WW));
    float mx = -1e30f, sm = 0.f;
    for (int i = tid; i < (HH * WW / 4); i += 256) {
        float4 v = p4[i];
        mx = fmaxf(mx, fmaxf(fmaxf(v.x, v.y), fmaxf(v.z, v.w)));
        sm += (v.x + v.y) + (v.z + v.w);
    }
#pragma unroll
    for (int o = 16; o; o >>= 1) {
        mx = fmaxf(mx, __shfl_xor_sync(0xffffffffu, mx, o));
        sm += __shfl_xor_sync(0xffffffffu, sm, o);
    }
    int w = tid >> 5, l = tid & 31;
    if (l == 0) { smx[w] = mx; ssm[w] = sm; }
    __syncthreads();
    if (tid == 0) {
        float M = smx[0], S = ssm[0];
#pragma unroll
        for (int i = 1; i < 8; i++) { M = fmaxf(M, smx[i]); S += ssm[i]; }
        g_pooled[bc] = M + S * (1.0f / (HH * WW));
        __threadfence();                                   // release g_pooled
        unsigned int old = atomicAdd(&g_done, 1u);
        s_last = (old == (unsigned)(BATCH * DIM - 1)) ? 1 : 0;
    }
    __syncthreads();
    if (!s_last) return;

    // ---- last block: gate ----
    __threadfence();                                       // acquire g_pooled
    if (tid == 0) g_done = 0;                              // reset for replay
    if (tid < BATCH * NEXP) {
        int b = tid / NEXP, e = tid - b * NEXP;
        const float* p = g_pooled + b * DIM;
        float d0 = b_fc0[e], d1 = b_fc1[e];
        for (int c = 0; c < DIM; c++) {
            float pv = p[c];
            d0 = fmaf(pv, w_fc0[e * DIM + c], d0);
            d1 = fmaf(pv, w_fc1[e * DIM + c], d1);
        }
        sh_g[b][e]  = (d1 >= 0.f) ? d1 : 0.2f * d1;                  // leaky_relu 0.2
        sh_nz[b][e] = fmaxf(d0, 0.f) + log1pf(expf(-fabsf(d0)));     // stable softplus
    }
    __syncthreads();
    if (tid < BATCH) {
        int b = tid;
        float g[NEXP], nz[NEXP];
#pragma unroll
        for (int e = 0; e < NEXP; e++) { g[e] = sh_g[b][e]; nz[e] = sh_nz[b][e]; }
        float mu = 0.f;
#pragma unroll
        for (int e = 0; e < NEXP; e++) mu += nz[e];
        mu *= (1.0f / NEXP);
        float var = 0.f;
#pragma unroll
        for (int e = 0; e < NEXP; e++) { float d = nz[e] - mu; var += d * d; }
        float sd = sqrtf(var / (NEXP - 1));                          // ddof=1
        float sc[NEXP];
#pragma unroll
        for (int e = 0; e < NEXP; e++) sc[e] = g[e] + (nz[e] - mu) / sd;

        bool used[NEXP] = {false, false, false, false, false, false};
        int idx[TOPK];
#pragma unroll
        for (int k = 0; k < TOPK; k++) {
            float best = -1e30f; int bi = 0;
#pragma unroll
            for (int e = 0; e < NEXP; e++)
                if (!used[e] && sc[e] > best) { best = sc[e]; bi = e; }
            used[bi] = true;
            idx[k] = bi;
        }
        float m = fmaxf(g[idx[0]], fmaxf(g[idx[1]], g[idx[2]]));
        float ex[TOPK], s = 0.f;
#pragma unroll
        for (int k = 0; k < TOPK; k++) { ex[k] = expf(g[idx[k]] - m); s += ex[k]; }
        float inv = 1.0f / s;
#pragma unroll
        for (int k = 0; k < TOPK; k++) {
            g_idx[b * TOPK + k] = idx[k];
            g_w[b * TOPK + k]   = ex[k] * inv;
        }
    }
}

// ---------------------------------------------------------------
// Kernel C: fused conv1 -> relu -> conv2 -> weighted sum (f32x2).
// Exact R4 inner code (best: 168us) + vectorized tile loader.
// 96 threads, thread t owns output column pair (2t, 2t+1), 16-row tile.
// ---------------------------------------------------------------
#define INW 196
#define INW2 98

struct P3 { u64 p0, p1, p2; };

__device__ __forceinline__ P3 load3(const float2* row, int t) {
    float2 L = row[t];       // idx (2t, 2t+1)   = cols (2t-1, 2t)
    float2 R = row[t + 1];   // idx (2t+2, 2t+3) = cols (2t+1, 2t+2)
    P3 r;
    r.p0 = pk2(L.x, L.y);
    r.p1 = pk2(L.y, R.x);
    r.p2 = pk2(R.x, R.y);
    return r;
}

__global__ __launch_bounds__(96) void moe_kernel(
    const float* __restrict__ x,
    const float* __restrict__ ew1, const float* __restrict__ eb1,
    const float* __restrict__ ew2, const float* __restrict__ eb2,
    float* __restrict__ out)
{
    const int t  = threadIdx.x;             // 0..95, column pair (2t, 2t+1)
    const int h0 = blockIdx.x * 16;
    const int c  = blockIdx.y;
    const int b  = blockIdx.z;

    // x tile: rows h0-2..h0+17 (20), col j at idx j+1; idx 0 & 193 zero pad
    __shared__ __align__(16) float in_s[20 * INW];
    // relu(conv1) tile: rows h0-1..h0+16 (18), col j at idx j+1
    __shared__ __align__(16) float c1_s[18 * INW];

    // ---- vectorized tile load: 20 row passes, 1 coalesced float2 each ----
    const float* xp = x + (size_t)(b * DIM + c) * (HH * WW);
#pragma unroll 4
    for (int ri = 0; ri < 20; ri++) {
        const int h = h0 - 2 + ri;
        float2 v = make_float2(0.f, 0.f);
        if ((unsigned)h < (unsigned)HH)
            v = reinterpret_cast<const float2*>(xp + h * WW)[t];
        in_s[ri * INW + 2 * t + 1] = v.x;
        in_s[ri * INW + 2 * t + 2] = v.y;
        if (t == 0) { in_s[ri * INW + 0] = 0.f; in_s[ri * INW + 193] = 0.f; }
    }
    // c1 halo columns (col -1 at idx 0, col 192 at idx 193) are always zero
    if (t < 18) { c1_s[t * INW + 0] = 0.f; c1_s[t * INW + 193] = 0.f; }

    u64 acc[16];
#pragma unroll
    for (int r = 0; r < 16; r++) acc[r] = 0ull;
    __syncthreads();

    const float2* in2 = reinterpret_cast<const float2*>(in_s);
    const float2* c12 = reinterpret_cast<const float2*>(c1_s);

    for (int ki = 0; ki < TOPK; ki++) {
        const int   e   = g_idx[b * TOPK + ki];
        const float cof = g_w[b * TOPK + ki];
        const float* w1 = ew1 + ((size_t)e * DIM + c) * 9;
        const float* w2 = ew2 + ((size_t)e * DIM + c) * 9;

        // ---- conv1 + relu -> c1_s ----
        {
            u64 K0 = pk2(w1[0], w1[0]), K1 = pk2(w1[1], w1[1]), K2 = pk2(w1[2], w1[2]);
            u64 K3 = pk2(w1[3], w1[3]), K4 = pk2(w1[4], w1[4]), K5 = pk2(w1[5], w1[5]);
            u64 K6 = pk2(w1[6], w1[6]), K7 = pk2(w1[7], w1[7]), K8 = pk2(w1[8], w1[8]);
            float b1v = eb1[e * DIM + c];
            u64 B1 = pk2(b1v, b1v);

            P3 A = load3(in2 + 0 * INW2, t);
            P3 B = load3(in2 + 1 * INW2, t);
#pragma unroll
            for (int r = 0; r < 18; r++) {
                P3 C = load3(in2 + (r + 2) * INW2, t);
                u64 v = fma2(K0, A.p0, fma2(K1, A.p1, fma2(K2, A.p2,
                        fma2(K3, B.p0, fma2(K4, B.p1, fma2(K5, B.p2,
                        fma2(K6, C.p0, fma2(K7, C.p1, fma2(K8, C.p2, B1)))))))));
                float v0, v1; upk2(v, v0, v1);
                const int hr = h0 + r - 1;
                const bool hok = (unsigned)hr < (unsigned)HH;
                // conv2's zero padding lives in the conv1-output domain
                c1_s[r * INW + 2 * t + 1] = hok ? fmaxf(v0, 0.f) : 0.f;
                c1_s[r * INW + 2 * t + 2] = hok ? fmaxf(v1, 0.f) : 0.f;
                A = B; B = C;
            }
        }
        __syncthreads();

        // ---- conv2 (weights pre-scaled by gate coeff), accumulate ----
        {
            u64 S0 = pk2(cof * w2[0], cof * w2[0]), S1 = pk2(cof * w2[1], cof * w2[1]);
            u64 S2 = pk2(cof * w2[2], cof * w2[2]), S3 = pk2(cof * w2[3], cof * w2[3]);
            u64 S4 = pk2(cof * w2[4], cof * w2[4]), S5 = pk2(cof * w2[5], cof * w2[5]);
            u64 S6 = pk2(cof * w2[6], cof * w2[6]), S7 = pk2(cof * w2[7], cof * w2[7]);
            u64 S8 = pk2(cof * w2[8], cof * w2[8]);
            float bbv = cof * eb2[e * DIM + c];
            u64 BB = pk2(bbv, bbv);

            P3 A = load3(c12 + 0 * INW2, t);
            P3 B = load3(c12 + 1 * INW2, t);
#pragma unroll
            for (int r = 0; r < 16; r++) {
                P3 C = load3(c12 + (r + 2) * INW2, t);
                acc[r] = fma2(S0, A.p0, fma2(S1, A.p1, fma2(S2, A.p2,
                         fma2(S3, B.p0, fma2(S4, B.p1, fma2(S5, B.p2,
                         fma2(S6, C.p0, fma2(S7, C.p1, fma2(S8, C.p2,
                         add2(acc[r], BB))))))))));
                A = B; B = C;
            }
        }
        __syncthreads();
    }

    float* op = out + (size_t)(b * DIM + c) * (HH * WW) + h0 * WW + 2 * t;
#pragma unroll
    for (int r = 0; r < 16; r++) {
        float o0, o1; upk2(acc[r], o0, o1);
        reinterpret_cast<float2*>(op + r * WW)[0] = make_float2(o0, o1);
    }
}

// ---------------------------------------------------------------
extern "C" void kernel_launch(void* const* d_in, const int* in_sizes, int n_in,
                              void* d_out, int out_size) {
    const float* x     = (const float*)d_in[0];
    const float* w_fc0 = (const float*)d_in[1];
    const float* b_fc0 = (const float*)d_in[2];
    const float* w_fc1 = (const float*)d_in[3];
    const float* b_fc1 = (const float*)d_in[4];
    const float* ew1   = (const float*)d_in[5];
    const float* eb1   = (const float*)d_in[6];
    const float* ew2   = (const float*)d_in[7];
    const float* eb2   = (const float*)d_in[8];
    float* out = (float*)d_out;

    pool_gate_kernel<<<BATCH * DIM, 256>>>(x, w_fc0, b_fc0, w_fc1, b_fc1);
    dim3 grid(HH / 16, DIM, BATCH);
    moe_kernel<<<grid, 96>>>(x, ew1, eb1, ew2, eb2, out);
}

// round 11
// speedup vs baseline: 1.4294x; 1.0509x over previous
#include <cuda_runtime.h>
#include <cuda_bf16.h>
#include <math.h>

#define BATCH 8
#define DIM 96
#define HH 192
#define WW 192
#define NEXP 6
#define TOPK 3

typedef unsigned long long u64;

// ---------- packed f32x2 helpers (sm_103a) ----------
__device__ __forceinline__ u64 pk2(float lo, float hi) {
    u64 d; asm("mov.b64 %0, {%1, %2};" : "=l"(d) : "f"(lo), "f"(hi)); return d;
}
__device__ __forceinline__ void upk2(u64 d, float& lo, float& hi) {
    asm("mov.b64 {%0, %1}, %2;" : "=f"(lo), "=f"(hi) : "l"(d));
}
__device__ __forceinline__ u64 fma2(u64 a, u64 b, u64 c) {
    u64 d; asm("fma.rn.f32x2 %0, %1, %2, %3;" : "=l"(d) : "l"(a), "l"(b), "l"(c)); return d;
}
__device__ __forceinline__ u64 add2(u64 a, u64 b) {
    u64 d; asm("add.rn.f32x2 %0, %1, %2;" : "=l"(d) : "l"(a), "l"(b)); return d;
}

// ---------- device scratch ----------
__device__ float g_pooled[BATCH * DIM];
__device__ int   g_idx[BATCH * TOPK];
__device__ float g_w[BATCH * TOPK];
__device__ unsigned int g_done = 0;   // self-resetting completion counter

// ---------------------------------------------------------------
// Kernel A: fused pooling + gate (last-block pattern, self-resetting).
// ---------------------------------------------------------------
__global__ __launch_bounds__(256) void pool_gate_kernel(
    const float* __restrict__ x,
    const float* __restrict__ w_fc0, const float* __restrict__ b_fc0,
    const float* __restrict__ w_fc1, const float* __restrict__ b_fc1)
{
    __shared__ float smx[8], ssm[8];
    __shared__ int   s_last;
    __shared__ float sh_g[BATCH][NEXP], sh_nz[BATCH][NEXP];

    const int bc = blockIdx.x;
    const int tid = threadIdx.x;
    const float4* p4 = reinterpret_cast<const float4*>(x + (size_t)bc * (HH * WW));
    float mx = -1e30f, sm = 0.f;
    for (int i = tid; i < (HH * WW / 4); i += 256) {
        float4 v = p4[i];
        mx = fmaxf(mx, fmaxf(fmaxf(v.x, v.y), fmaxf(v.z, v.w)));
        sm += (v.x + v.y) + (v.z + v.w);
    }
#pragma unroll
    for (int o = 16; o; o >>= 1) {
        mx = fmaxf(mx, __shfl_xor_sync(0xffffffffu, mx, o));
        sm += __shfl_xor_sync(0xffffffffu, sm, o);
    }
    int w = tid >> 5, l = tid & 31;
    if (l == 0) { smx[w] = mx; ssm[w] = sm; }
    __syncthreads();
    if (tid == 0) {
        float M = smx[0], S = ssm[0];
#pragma unroll
        for (int i = 1; i < 8; i++) { M = fmaxf(M, smx[i]); S += ssm[i]; }
        g_pooled[bc] = M + S * (1.0f / (HH * WW));
        __threadfence();                                   // release g_pooled
        unsigned int old = atomicAdd(&g_done, 1u);
        s_last = (old == (unsigned)(BATCH * DIM - 1)) ? 1 : 0;
    }
    __syncthreads();
    if (!s_last) return;

    // ---- last block: gate ----
    __threadfence();                                       // acquire g_pooled
    if (tid == 0) g_done = 0;                              // reset for replay
    if (tid < BATCH * NEXP) {
        int b = tid / NEXP, e = tid - b * NEXP;
        const float* p = g_pooled + b * DIM;
        float d0 = b_fc0[e], d1 = b_fc1[e];
        for (int c = 0; c < DIM; c++) {
            float pv = p[c];
            d0 = fmaf(pv, w_fc0[e * DIM + c], d0);
            d1 = fmaf(pv, w_fc1[e * DIM + c], d1);
        }
        sh_g[b][e]  = (d1 >= 0.f) ? d1 : 0.2f * d1;                  // leaky_relu 0.2
        sh_nz[b][e] = fmaxf(d0, 0.f) + log1pf(expf(-fabsf(d0)));     // stable softplus
    }
    __syncthreads();
    if (tid < BATCH) {
        int b = tid;
        float g[NEXP], nz[NEXP];
#pragma unroll
        for (int e = 0; e < NEXP; e++) { g[e] = sh_g[b][e]; nz[e] = sh_nz[b][e]; }
        float mu = 0.f;
#pragma unroll
        for (int e = 0; e < NEXP; e++) mu += nz[e];
        mu *= (1.0f / NEXP);
        float var = 0.f;
#pragma unroll
        for (int e = 0; e < NEXP; e++) { float d = nz[e] - mu; var += d * d; }
        float sd = sqrtf(var / (NEXP - 1));                          // ddof=1
        float sc[NEXP];
#pragma unroll
        for (int e = 0; e < NEXP; e++) sc[e] = g[e] + (nz[e] - mu) / sd;

        bool used[NEXP] = {false, false, false, false, false, false};
        int idx[TOPK];
#pragma unroll
        for (int k = 0; k < TOPK; k++) {
            float best = -1e30f; int bi = 0;
#pragma unroll
            for (int e = 0; e < NEXP; e++)
                if (!used[e] && sc[e] > best) { best = sc[e]; bi = e; }
            used[bi] = true;
            idx[k] = bi;
        }
        float m = fmaxf(g[idx[0]], fmaxf(g[idx[1]], g[idx[2]]));
        float ex[TOPK], s = 0.f;
#pragma unroll
        for (int k = 0; k < TOPK; k++) { ex[k] = expf(g[idx[k]] - m); s += ex[k]; }
        float inv = 1.0f / s;
#pragma unroll
        for (int k = 0; k < TOPK; k++) {
            g_idx[b * TOPK + k] = idx[k];
            g_w[b * TOPK + k]   = ex[k] * inv;
        }
    }
}

// ---------------------------------------------------------------
// Kernel C: fused conv1 -> relu -> conv2 -> weighted sum (f32x2).
// SCATTER form: each source row feeds three INDEPENDENT 3-deep fma2
// chains (dest rows r, r-1, r-2) instead of one 9-deep chain, cutting
// per-iteration latency exposure ~3x. Same smem layout/traffic as the
// R10 kernel (occupancy unchanged at 7 blocks/SM).
// ---------------------------------------------------------------
#define INW 196
#define INW2 98

struct P3 { u64 p0, p1, p2; };

__device__ __forceinline__ P3 load3(const float2* row, int t) {
    float2 L = row[t];       // idx (2t, 2t+1)   = cols (2t-1, 2t)
    float2 R = row[t + 1];   // idx (2t+2, 2t+3) = cols (2t+1, 2t+2)
    P3 r;
    r.p0 = pk2(L.x, L.y);
    r.p1 = pk2(L.y, R.x);
    r.p2 = pk2(R.x, R.y);
    return r;
}

__global__ __launch_bounds__(96) void moe_kernel(
    const float* __restrict__ x,
    const float* __restrict__ ew1, const float* __restrict__ eb1,
    const float* __restrict__ ew2, const float* __restrict__ eb2,
    float* __restrict__ out)
{
    const int t  = threadIdx.x;             // 0..95, column pair (2t, 2t+1)
    const int h0 = blockIdx.x * 16;
    const int c  = blockIdx.y;
    const int b  = blockIdx.z;

    // x tile: rows h0-2..h0+17 (20), col j at idx j+1; idx 0 & 193 zero pad
    __shared__ __align__(16) float in_s[20 * INW];
    // relu(conv1) tile: rows h0-1..h0+16 (18), col j at idx j+1
    __shared__ __align__(16) float c1_s[18 * INW];

    // ---- vectorized tile load: 20 row passes, 1 coalesced float2 each ----
    const float* xp = x + (size_t)(b * DIM + c) * (HH * WW);
#pragma unroll 4
    for (int ri = 0; ri < 20; ri++) {
        const int h = h0 - 2 + ri;
        float2 v = make_float2(0.f, 0.f);
        if ((unsigned)h < (unsigned)HH)
            v = reinterpret_cast<const float2*>(xp + h * WW)[t];
        in_s[ri * INW + 2 * t + 1] = v.x;
        in_s[ri * INW + 2 * t + 2] = v.y;
        if (t == 0) { in_s[ri * INW + 0] = 0.f; in_s[ri * INW + 193] = 0.f; }
    }
    // c1 halo columns (col -1 at idx 0, col 192 at idx 193) are always zero
    if (t < 18) { c1_s[t * INW + 0] = 0.f; c1_s[t * INW + 193] = 0.f; }

    u64 acc[16];
#pragma unroll
    for (int r = 0; r < 16; r++) acc[r] = 0ull;
    __syncthreads();

    const float2* in2 = reinterpret_cast<const float2*>(in_s);
    const float2* c12 = reinterpret_cast<const float2*>(c1_s);

    for (int ki = 0; ki < TOPK; ki++) {
        const int   e   = g_idx[b * TOPK + ki];
        const float cof = g_w[b * TOPK + ki];
        const float* w1 = ew1 + ((size_t)e * DIM + c) * 9;
        const float* w2 = ew2 + ((size_t)e * DIM + c) * 9;

        // ---- conv1 + relu -> c1_s (scatter, 3-slot circular accumulator) ----
        // c1[j] = K012*in[j] + K345*in[j+1] + K678*in[j+2]; source row ri
        // contributes K012->c1[ri], K345->c1[ri-1], K678->c1[ri-2].
        {
            const u64 K0 = pk2(w1[0], w1[0]), K1 = pk2(w1[1], w1[1]), K2 = pk2(w1[2], w1[2]);
            const u64 K3 = pk2(w1[3], w1[3]), K4 = pk2(w1[4], w1[4]), K5 = pk2(w1[5], w1[5]);
            const u64 K6 = pk2(w1[6], w1[6]), K7 = pk2(w1[7], w1[7]), K8 = pk2(w1[8], w1[8]);
            const float b1v = eb1[e * DIM + c];
            const u64 B1 = pk2(b1v, b1v);

            u64 s[3];
#pragma unroll
            for (int ri = 0; ri < 20; ri++) {
                P3 X = load3(in2 + ri * INW2, t);
                if (ri >= 2) {          // finish c1 row (ri-2) and store
                    u64 v = fma2(K6, X.p0, fma2(K7, X.p1, fma2(K8, X.p2, s[(ri - 2) % 3])));
                    float v0, v1; upk2(v, v0, v1);
                    const int hr = h0 + (ri - 2) - 1;
                    const bool hok = (unsigned)hr < (unsigned)HH;
                    // conv2's zero padding lives in the conv1-output domain
                    c1_s[(ri - 2) * INW + 2 * t + 1] = hok ? fmaxf(v0, 0.f) : 0.f;
                    c1_s[(ri - 2) * INW + 2 * t + 2] = hok ? fmaxf(v1, 0.f) : 0.f;
                }
                if (ri >= 1 && ri <= 18)  // middle taps of c1 row (ri-1)
                    s[(ri - 1) % 3] = fma2(K3, X.p0, fma2(K4, X.p1, fma2(K5, X.p2, s[(ri - 1) % 3])));
                if (ri <= 17)             // start c1 row ri
                    s[ri % 3] = fma2(K0, X.p0, fma2(K1, X.p1, fma2(K2, X.p2, B1)));
            }
        }
        __syncthreads();

        // ---- conv2 (scatter into acc[16], weights pre-scaled by cof) ----
        // c1 row rr contributes S012->acc[rr], S345->acc[rr-1], S678->acc[rr-2].
        {
            const u64 S0 = pk2(cof * w2[0], cof * w2[0]), S1 = pk2(cof * w2[1], cof * w2[1]);
            const u64 S2 = pk2(cof * w2[2], cof * w2[2]), S3 = pk2(cof * w2[3], cof * w2[3]);
            const u64 S4 = pk2(cof * w2[4], cof * w2[4]), S5 = pk2(cof * w2[5], cof * w2[5]);
            const u64 S6 = pk2(cof * w2[6], cof * w2[6]), S7 = pk2(cof * w2[7], cof * w2[7]);
            const u64 S8 = pk2(cof * w2[8], cof * w2[8]);
            const float bbv = cof * eb2[e * DIM + c];
            const u64 BB = pk2(bbv, bbv);

#pragma unroll
            for (int rr = 0; rr < 18; rr++) {
                P3 X = load3(c12 + rr * INW2, t);
                if (rr <= 15)
                    acc[rr]     = fma2(S0, X.p0, fma2(S1, X.p1, fma2(S2, X.p2, acc[rr])));
                if (rr >= 1 && rr <= 16)
                    acc[rr - 1] = fma2(S3, X.p0, fma2(S4, X.p1, fma2(S5, X.p2, acc[rr - 1])));
                if (rr >= 2)
                    acc[rr - 2] = fma2(S6, X.p0, fma2(S7, X.p1, fma2(S8, X.p2, acc[rr - 2])));
            }
#pragma unroll
            for (int o = 0; o < 16; o++) acc[o] = add2(acc[o], BB);
        }
        __syncthreads();
    }

    float* op = out + (size_t)(b * DIM + c) * (HH * WW) + h0 * WW + 2 * t;
#pragma unroll
    for (int r = 0; r < 16; r++) {
        float o0, o1; upk2(acc[r], o0, o1);
        reinterpret_cast<float2*>(op + r * WW)[0] = make_float2(o0, o1);
    }
}

// ---------------------------------------------------------------
extern "C" void kernel_launch(void* const* d_in, const int* in_sizes, int n_in,
                              void* d_out, int out_size) {
    const float* x     = (const float*)d_in[0];
    const float* w_fc0 = (const float*)d_in[1];
    const float* b_fc0 = (const float*)d_in[2];
    const float* w_fc1 = (const float*)d_in[3];
    const float* b_fc1 = (const float*)d_in[4];
    const float* ew1   = (const float*)d_in[5];
    const float* eb1   = (const float*)d_in[6];
    const float* ew2   = (const float*)d_in[7];
    const float* eb2   = (const float*)d_in[8];
    float* out = (float*)d_out;

    pool_gate_kernel<<<BATCH * DIM, 256>>>(x, w_fc0, b_fc0, w_fc1, b_fc1);
    dim3 grid(HH / 16, DIM, BATCH);
    moe_kernel<<<grid, 96>>>(x, ew1, eb1, ew2, eb2, out);
}

// round 12
// speedup vs baseline: 1.4891x; 1.0418x over previous
#include <cuda_runtime.h>
#include <cuda_bf16.h>
#include <math.h>

#define BATCH 8
#define DIM 96
#define HH 192
#define WW 192
#define NEXP 6
#define TOPK 3

#define TR 8              // output rows per tile
#define NIN (TR + 4)      // input rows per tile (12)
#define NC1 (TR + 2)      // conv1 rows per tile (10)

typedef unsigned long long u64;

// ---------- packed f32x2 helpers (sm_103a) ----------
__device__ __forceinline__ u64 pk2(float lo, float hi) {
    u64 d; asm("mov.b64 %0, {%1, %2};" : "=l"(d) : "f"(lo), "f"(hi)); return d;
}
__device__ __forceinline__ void upk2(u64 d, float& lo, float& hi) {
    asm("mov.b64 {%0, %1}, %2;" : "=f"(lo), "=f"(hi) : "l"(d));
}
__device__ __forceinline__ u64 fma2(u64 a, u64 b, u64 c) {
    u64 d; asm("fma.rn.f32x2 %0, %1, %2, %3;" : "=l"(d) : "l"(a), "l"(b), "l"(c)); return d;
}
__device__ __forceinline__ u64 add2(u64 a, u64 b) {
    u64 d; asm("add.rn.f32x2 %0, %1, %2;" : "=l"(d) : "l"(a), "l"(b)); return d;
}

// ---------- device scratch ----------
__device__ float g_pooled[BATCH * DIM];
__device__ int   g_idx[BATCH * TOPK];
__device__ float g_w[BATCH * TOPK];
__device__ unsigned int g_done = 0;   // self-resetting completion counter

// ---------------------------------------------------------------
// Kernel A: fused pooling + gate (last-block pattern, self-resetting).
// ---------------------------------------------------------------
__global__ __launch_bounds__(256) void pool_gate_kernel(
    const float* __restrict__ x,
    const float* __restrict__ w_fc0, const float* __restrict__ b_fc0,
    const float* __restrict__ w_fc1, const float* __restrict__ b_fc1)
{
    __shared__ float smx[8], ssm[8];
    __shared__ int   s_last;
    __shared__ float sh_g[BATCH][NEXP], sh_nz[BATCH][NEXP];

    const int bc = blockIdx.x;
    const int tid = threadIdx.x;
    const float4* p4 = reinterpret_cast<const float4*>(x + (size_t)bc * (HH * WW));
    float mx = -1e30f, sm = 0.f;
    for (int i = tid; i < (HH * WW / 4); i += 256) {
        float4 v = p4[i];
        mx = fmaxf(mx, fmaxf(fmaxf(v.x, v.y), fmaxf(v.z, v.w)));
        sm += (v.x + v.y) + (v.z + v.w);
    }
#pragma unroll
    for (int o = 16; o; o >>= 1) {
        mx = fmaxf(mx, __shfl_xor_sync(0xffffffffu, mx, o));
        sm += __shfl_xor_sync(0xffffffffu, sm, o);
    }
    int w = tid >> 5, l = tid & 31;
    if (l == 0) { smx[w] = mx; ssm[w] = sm; }
    __syncthreads();
    if (tid == 0) {
        float M = smx[0], S = ssm[0];
#pragma unroll
        for (int i = 1; i < 8; i++) { M = fmaxf(M, smx[i]); S += ssm[i]; }
        g_pooled[bc] = M + S * (1.0f / (HH * WW));
        __threadfence();                                   // release g_pooled
        unsigned int old = atomicAdd(&g_done, 1u);
        s_last = (old == (unsigned)(BATCH * DIM - 1)) ? 1 : 0;
    }
    __syncthreads();
    if (!s_last) return;

    // ---- last block: gate ----
    __threadfence();                                       // acquire g_pooled
    if (tid == 0) g_done = 0;                              // reset for replay
    if (tid < BATCH * NEXP) {
        int b = tid / NEXP, e = tid - b * NEXP;
        const float* p = g_pooled + b * DIM;
        float d0 = b_fc0[e], d1 = b_fc1[e];
        for (int c = 0; c < DIM; c++) {
            float pv = p[c];
            d0 = fmaf(pv, w_fc0[e * DIM + c], d0);
            d1 = fmaf(pv, w_fc1[e * DIM + c], d1);
        }
        sh_g[b][e]  = (d1 >= 0.f) ? d1 : 0.2f * d1;                  // leaky_relu 0.2
        sh_nz[b][e] = fmaxf(d0, 0.f) + log1pf(expf(-fabsf(d0)));     // stable softplus
    }
    __syncthreads();
    if (tid < BATCH) {
        int b = tid;
        float g[NEXP], nz[NEXP];
#pragma unroll
        for (int e = 0; e < NEXP; e++) { g[e] = sh_g[b][e]; nz[e] = sh_nz[b][e]; }
        float mu = 0.f;
#pragma unroll
        for (int e = 0; e < NEXP; e++) mu += nz[e];
        mu *= (1.0f / NEXP);
        float var = 0.f;
#pragma unroll
        for (int e = 0; e < NEXP; e++) { float d = nz[e] - mu; var += d * d; }
        float sd = sqrtf(var / (NEXP - 1));                          // ddof=1
        float sc[NEXP];
#pragma unroll
        for (int e = 0; e < NEXP; e++) sc[e] = g[e] + (nz[e] - mu) / sd;

        bool used[NEXP] = {false, false, false, false, false, false};
        int idx[TOPK];
#pragma unroll
        for (int k = 0; k < TOPK; k++) {
            float best = -1e30f; int bi = 0;
#pragma unroll
            for (int e = 0; e < NEXP; e++)
                if (!used[e] && sc[e] > best) { best = sc[e]; bi = e; }
            used[bi] = true;
            idx[k] = bi;
        }
        float m = fmaxf(g[idx[0]], fmaxf(g[idx[1]], g[idx[2]]));
        float ex[TOPK], s = 0.f;
#pragma unroll
        for (int k = 0; k < TOPK; k++) { ex[k] = expf(g[idx[k]] - m); s += ex[k]; }
        float inv = 1.0f / s;
#pragma unroll
        for (int k = 0; k < TOPK; k++) {
            g_idx[b * TOPK + k] = idx[k];
            g_w[b * TOPK + k]   = ex[k] * inv;
        }
    }
}

// ---------------------------------------------------------------
// Kernel C: fused conv1 -> relu -> conv2 -> weighted sum (f32x2).
// Scatter form (independent 3-deep fma2 chains). 8-row tiles: smem
// 17.3KB and ~64 regs -> ~10 blocks/SM (30 warps) vs 7 blocks before.
// ---------------------------------------------------------------
#define INW 196
#define INW2 98

struct P3 { u64 p0, p1, p2; };

__device__ __forceinline__ P3 load3(const float2* row, int t) {
    float2 L = row[t];       // idx (2t, 2t+1)   = cols (2t-1, 2t)
    float2 R = row[t + 1];   // idx (2t+2, 2t+3) = cols (2t+1, 2t+2)
    P3 r;
    r.p0 = pk2(L.x, L.y);
    r.p1 = pk2(L.y, R.x);
    r.p2 = pk2(R.x, R.y);
    return r;
}

__global__ __launch_bounds__(96) void moe_kernel(
    const float* __restrict__ x,
    const float* __restrict__ ew1, const float* __restrict__ eb1,
    const float* __restrict__ ew2, const float* __restrict__ eb2,
    float* __restrict__ out)
{
    const int t  = threadIdx.x;             // 0..95, column pair (2t, 2t+1)
    const int h0 = blockIdx.x * TR;
    const int c  = blockIdx.y;
    const int b  = blockIdx.z;

    // x tile: rows h0-2..h0+TR+1 (NIN), col j at idx j+1; idx 0 & 193 zero pad
    __shared__ __align__(16) float in_s[NIN * INW];
    // relu(conv1) tile: rows h0-1..h0+TR (NC1), col j at idx j+1
    __shared__ __align__(16) float c1_s[NC1 * INW];

    // ---- vectorized tile load: NIN row passes, 1 coalesced float2 each ----
    const float* xp = x + (size_t)(b * DIM + c) * (HH * WW);
#pragma unroll 4
    for (int ri = 0; ri < NIN; ri++) {
        const int h = h0 - 2 + ri;
        float2 v = make_float2(0.f, 0.f);
        if ((unsigned)h < (unsigned)HH)
            v = reinterpret_cast<const float2*>(xp + h * WW)[t];
        in_s[ri * INW + 2 * t + 1] = v.x;
        in_s[ri * INW + 2 * t + 2] = v.y;
        if (t == 0) { in_s[ri * INW + 0] = 0.f; in_s[ri * INW + 193] = 0.f; }
    }
    // c1 halo columns (col -1 at idx 0, col 192 at idx 193) are always zero
    if (t < NC1) { c1_s[t * INW + 0] = 0.f; c1_s[t * INW + 193] = 0.f; }

    u64 acc[TR];
#pragma unroll
    for (int r = 0; r < TR; r++) acc[r] = 0ull;
    __syncthreads();

    const float2* in2 = reinterpret_cast<const float2*>(in_s);
    const float2* c12 = reinterpret_cast<const float2*>(c1_s);

    for (int ki = 0; ki < TOPK; ki++) {
        const int   e   = g_idx[b * TOPK + ki];
        const float cof = g_w[b * TOPK + ki];
        const float* w1 = ew1 + ((size_t)e * DIM + c) * 9;
        const float* w2 = ew2 + ((size_t)e * DIM + c) * 9;

        // ---- conv1 + relu -> c1_s (scatter, 3-slot circular accumulator) ----
        {
            const u64 K0 = pk2(w1[0], w1[0]), K1 = pk2(w1[1], w1[1]), K2 = pk2(w1[2], w1[2]);
            const u64 K3 = pk2(w1[3], w1[3]), K4 = pk2(w1[4], w1[4]), K5 = pk2(w1[5], w1[5]);
            const u64 K6 = pk2(w1[6], w1[6]), K7 = pk2(w1[7], w1[7]), K8 = pk2(w1[8], w1[8]);
            const float b1v = eb1[e * DIM + c];
            const u64 B1 = pk2(b1v, b1v);

            u64 s[3];
#pragma unroll
            for (int ri = 0; ri < NIN; ri++) {
                P3 X = load3(in2 + ri * INW2, t);
                if (ri >= 2) {          // finish c1 row (ri-2) and store
                    u64 v = fma2(K6, X.p0, fma2(K7, X.p1, fma2(K8, X.p2, s[(ri - 2) % 3])));
                    float v0, v1; upk2(v, v0, v1);
                    const int hr = h0 + (ri - 2) - 1;
                    const bool hok = (unsigned)hr < (unsigned)HH;
                    // conv2's zero padding lives in the conv1-output domain
                    c1_s[(ri - 2) * INW + 2 * t + 1] = hok ? fmaxf(v0, 0.f) : 0.f;
                    c1_s[(ri - 2) * INW + 2 * t + 2] = hok ? fmaxf(v1, 0.f) : 0.f;
                }
                if (ri >= 1 && ri <= NC1)      // middle taps of c1 row (ri-1)
                    s[(ri - 1) % 3] = fma2(K3, X.p0, fma2(K4, X.p1, fma2(K5, X.p2, s[(ri - 1) % 3])));
                if (ri <= NC1 - 1)             // start c1 row ri
                    s[ri % 3] = fma2(K0, X.p0, fma2(K1, X.p1, fma2(K2, X.p2, B1)));
            }
        }
        __syncthreads();

        // ---- conv2 (scatter into acc[TR], weights pre-scaled by cof) ----
        {
            const u64 S0 = pk2(cof * w2[0], cof * w2[0]), S1 = pk2(cof * w2[1], cof * w2[1]);
            const u64 S2 = pk2(cof * w2[2], cof * w2[2]), S3 = pk2(cof * w2[3], cof * w2[3]);
            const u64 S4 = pk2(cof * w2[4], cof * w2[4]), S5 = pk2(cof * w2[5], cof * w2[5]);
            const u64 S6 = pk2(cof * w2[6], cof * w2[6]), S7 = pk2(cof * w2[7], cof * w2[7]);
            const u64 S8 = pk2(cof * w2[8], cof * w2[8]);
            const float bbv = cof * eb2[e * DIM + c];
            const u64 BB = pk2(bbv, bbv);

#pragma unroll
            for (int rr = 0; rr < NC1; rr++) {
                P3 X = load3(c12 + rr * INW2, t);
                if (rr <= TR - 1)
                    acc[rr]     = fma2(S0, X.p0, fma2(S1, X.p1, fma2(S2, X.p2, acc[rr])));
                if (rr >= 1 && rr <= TR)
                    acc[rr - 1] = fma2(S3, X.p0, fma2(S4, X.p1, fma2(S5, X.p2, acc[rr - 1])));
                if (rr >= 2)
                    acc[rr - 2] = fma2(S6, X.p0, fma2(S7, X.p1, fma2(S8, X.p2, acc[rr - 2])));
            }
#pragma unroll
            for (int o = 0; o < TR; o++) acc[o] = add2(acc[o], BB);
        }
        __syncthreads();
    }

    float* op = out + (size_t)(b * DIM + c) * (HH * WW) + h0 * WW + 2 * t;
#pragma unroll
    for (int r = 0; r < TR; r++) {
        float o0, o1; upk2(acc[r], o0, o1);
        reinterpret_cast<float2*>(op + r * WW)[0] = make_float2(o0, o1);
    }
}

// ---------------------------------------------------------------
extern "C" void kernel_launch(void* const* d_in, const int* in_sizes, int n_in,
                              void* d_out, int out_size) {
    const float* x     = (const float*)d_in[0];
    const float* w_fc0 = (const float*)d_in[1];
    const float* b_fc0 = (const float*)d_in[2];
    const float* w_fc1 = (const float*)d_in[3];
    const float* b_fc1 = (const float*)d_in[4];
    const float* ew1   = (const float*)d_in[5];
    const float* eb1   = (const float*)d_in[6];
    const float* ew2   = (const float*)d_in[7];
    const float* eb2   = (const float*)d_in[8];
    float* out = (float*)d_out;

    pool_gate_kernel<<<BATCH * DIM, 256>>>(x, w_fc0, b_fc0, w_fc1, b_fc1);
    dim3 grid(HH / TR, DIM, BATCH);
    moe_kernel<<<grid, 96>>>(x, ew1, eb1, ew2, eb2, out);
}

// round 13
// speedup vs baseline: 1.5124x; 1.0157x over previous
#include <cuda_runtime.h>
#include <cuda_bf16.h>
#include <cuda_fp16.h>
#include <math.h>

#define BATCH 8
#define DIM 96
#define HH 192
#define WW 192
#define NEXP 6
#define TOPK 3

#define TR 8              // output rows per tile
#define NIN (TR + 4)      // input rows per tile (12)
#define NC1 (TR + 2)      // conv1 rows per tile (10)

typedef unsigned long long u64;

// ---------- packed f32x2 helpers (sm_103a) ----------
__device__ __forceinline__ u64 pk2(float lo, float hi) {
    u64 d; asm("mov.b64 %0, {%1, %2};" : "=l"(d) : "f"(lo), "f"(hi)); return d;
}
__device__ __forceinline__ void upk2(u64 d, float& lo, float& hi) {
    asm("mov.b64 {%0, %1}, %2;" : "=f"(lo), "=f"(hi) : "l"(d));
}
__device__ __forceinline__ u64 fma2(u64 a, u64 b, u64 c) {
    u64 d; asm("fma.rn.f32x2 %0, %1, %2, %3;" : "=l"(d) : "l"(a), "l"(b), "l"(c)); return d;
}
__device__ __forceinline__ u64 add2(u64 a, u64 b) {
    u64 d; asm("add.rn.f32x2 %0, %1, %2;" : "=l"(d) : "l"(a), "l"(b)); return d;
}

// ---------- device scratch ----------
__device__ float g_pooled[BATCH * DIM];
__device__ int   g_idx[BATCH * TOPK];
__device__ float g_w[BATCH * TOPK];
__device__ unsigned int g_done = 0;   // self-resetting completion counter

// ---------------------------------------------------------------
// Kernel A: fused pooling + gate (last-block pattern, self-resetting).
// ---------------------------------------------------------------
__global__ __launch_bounds__(256) void pool_gate_kernel(
    const float* __restrict__ x,
    const float* __restrict__ w_fc0, const float* __restrict__ b_fc0,
    const float* __restrict__ w_fc1, const float* __restrict__ b_fc1)
{
    __shared__ float smx[8], ssm[8];
    __shared__ int   s_last;
    __shared__ float sh_g[BATCH][NEXP], sh_nz[BATCH][NEXP];

    const int bc = blockIdx.x;
    const int tid = threadIdx.x;
    const float4* p4 = reinterpret_cast<const float4*>(x + (size_t)bc * (HH * WW));
    float mx = -1e30f, sm = 0.f;
    for (int i = tid; i < (HH * WW / 4); i += 256) {
        float4 v = p4[i];
        mx = fmaxf(mx, fmaxf(fmaxf(v.x, v.y), fmaxf(v.z, v.w)));
        sm += (v.x + v.y) + (v.z + v.w);
    }
#pragma unroll
    for (int o = 16; o; o >>= 1) {
        mx = fmaxf(mx, __shfl_xor_sync(0xffffffffu, mx, o));
        sm += __shfl_xor_sync(0xffffffffu, sm, o);
    }
    int w = tid >> 5, l = tid & 31;
    if (l == 0) { smx[w] = mx; ssm[w] = sm; }
    __syncthreads();
    if (tid == 0) {
        float M = smx[0], S = ssm[0];
#pragma unroll
        for (int i = 1; i < 8; i++) { M = fmaxf(M, smx[i]); S += ssm[i]; }
        g_pooled[bc] = M + S * (1.0f / (HH * WW));
        __threadfence();                                   // release g_pooled
        unsigned int old = atomicAdd(&g_done, 1u);
        s_last = (old == (unsigned)(BATCH * DIM - 1)) ? 1 : 0;
    }
    __syncthreads();
    if (!s_last) return;

    // ---- last block: gate ----
    __threadfence();                                       // acquire g_pooled
    if (tid == 0) g_done = 0;                              // reset for replay
    if (tid < BATCH * NEXP) {
        int b = tid / NEXP, e = tid - b * NEXP;
        const float* p = g_pooled + b * DIM;
        float d0 = b_fc0[e], d1 = b_fc1[e];
        for (int c = 0; c < DIM; c++) {
            float pv = p[c];
            d0 = fmaf(pv, w_fc0[e * DIM + c], d0);
            d1 = fmaf(pv, w_fc1[e * DIM + c], d1);
        }
        sh_g[b][e]  = (d1 >= 0.f) ? d1 : 0.2f * d1;                  // leaky_relu 0.2
        sh_nz[b][e] = fmaxf(d0, 0.f) + log1pf(expf(-fabsf(d0)));     // stable softplus
    }
    __syncthreads();
    if (tid < BATCH) {
        int b = tid;
        float g[NEXP], nz[NEXP];
#pragma unroll
        for (int e = 0; e < NEXP; e++) { g[e] = sh_g[b][e]; nz[e] = sh_nz[b][e]; }
        float mu = 0.f;
#pragma unroll
        for (int e = 0; e < NEXP; e++) mu += nz[e];
        mu *= (1.0f / NEXP);
        float var = 0.f;
#pragma unroll
        for (int e = 0; e < NEXP; e++) { float d = nz[e] - mu; var += d * d; }
        float sd = sqrtf(var / (NEXP - 1));                          // ddof=1
        float sc[NEXP];
#pragma unroll
        for (int e = 0; e < NEXP; e++) sc[e] = g[e] + (nz[e] - mu) / sd;

        bool used[NEXP] = {false, false, false, false, false, false};
        int idx[TOPK];
#pragma unroll
        for (int k = 0; k < TOPK; k++) {
            float best = -1e30f; int bi = 0;
#pragma unroll
            for (int e = 0; e < NEXP; e++)
                if (!used[e] && sc[e] > best) { best = sc[e]; bi = e; }
            used[bi] = true;
            idx[k] = bi;
        }
        float m = fmaxf(g[idx[0]], fmaxf(g[idx[1]], g[idx[2]]));
        float ex[TOPK], s = 0.f;
#pragma unroll
        for (int k = 0; k < TOPK; k++) { ex[k] = expf(g[idx[k]] - m); s += ex[k]; }
        float inv = 1.0f / s;
#pragma unroll
        for (int k = 0; k < TOPK; k++) {
            g_idx[b * TOPK + k] = idx[k];
            g_w[b * TOPK + k]   = ex[k] * inv;
        }
    }
}

// ---------------------------------------------------------------
// Kernel C: fused conv1 -> relu -> conv2 -> weighted sum (f32x2).
// Scatter form, 8-row tiles. c1 is stored as fp16x2 PAIRS:
//   pair j = (col 2j, col 2j+1) at u32 index j+1 (idx 0 & 97 zero halo).
// conv1 store = 1 conflict-free STS.32/row (was 2 conflicted STS.32);
// conv2 load  = 3 conflict-free LDS.32/row (was 2 LDS.64).
// L1 wavefronts per expert drop 128 -> 88.
// ---------------------------------------------------------------
#define INW 196
#define INW2 98
#define C1PW 100   // u32 pairs per c1 row (96 pairs + halos + pad)

struct P3 { u64 p0, p1, p2; };

__device__ __forceinline__ P3 load3(const float2* row, int t) {
    float2 L = row[t];       // idx (2t, 2t+1)   = cols (2t-1, 2t)
    float2 R = row[t + 1];   // idx (2t+2, 2t+3) = cols (2t+1, 2t+2)
    P3 r;
    r.p0 = pk2(L.x, L.y);
    r.p1 = pk2(L.y, R.x);
    r.p2 = pk2(R.x, R.y);
    return r;
}

__global__ __launch_bounds__(96) void moe_kernel(
    const float* __restrict__ x,
    const float* __restrict__ ew1, const float* __restrict__ eb1,
    const float* __restrict__ ew2, const float* __restrict__ eb2,
    float* __restrict__ out)
{
    const int t  = threadIdx.x;             // 0..95, column pair (2t, 2t+1)
    const int h0 = blockIdx.x * TR;
    const int c  = blockIdx.y;
    const int b  = blockIdx.z;

    // x tile: rows h0-2..h0+TR+1 (NIN), col j at idx j+1; idx 0 & 193 zero pad
    __shared__ __align__(16) float in_s[NIN * INW];
    // relu(conv1) as fp16x2 pairs: rows h0-1..h0+TR (NC1)
    __shared__ __half2 c1h[NC1 * C1PW];

    // ---- vectorized tile load: NIN row passes, 1 coalesced float2 each ----
    const float* xp = x + (size_t)(b * DIM + c) * (HH * WW);
#pragma unroll 4
    for (int ri = 0; ri < NIN; ri++) {
        const int h = h0 - 2 + ri;
        float2 v = make_float2(0.f, 0.f);
        if ((unsigned)h < (unsigned)HH)
            v = reinterpret_cast<const float2*>(xp + h * WW)[t];
        in_s[ri * INW + 2 * t + 1] = v.x;
        in_s[ri * INW + 2 * t + 2] = v.y;
        if (t == 0) { in_s[ri * INW + 0] = 0.f; in_s[ri * INW + 193] = 0.f; }
    }
    // c1 halo pairs: idx 0 = cols(-2,-1), idx 97 = cols(192,193): always zero
    if (t < NC1) {
        c1h[t * C1PW + 0]  = __floats2half2_rn(0.f, 0.f);
        c1h[t * C1PW + 97] = __floats2half2_rn(0.f, 0.f);
    }

    u64 acc[TR];
#pragma unroll
    for (int r = 0; r < TR; r++) acc[r] = 0ull;
    __syncthreads();

    const float2* in2 = reinterpret_cast<const float2*>(in_s);

    for (int ki = 0; ki < TOPK; ki++) {
        const int   e   = g_idx[b * TOPK + ki];
        const float cof = g_w[b * TOPK + ki];
        const float* w1 = ew1 + ((size_t)e * DIM + c) * 9;
        const float* w2 = ew2 + ((size_t)e * DIM + c) * 9;

        // ---- conv1 + relu -> c1h (scatter, 3-slot circular accumulator) ----
        {
            const u64 K0 = pk2(w1[0], w1[0]), K1 = pk2(w1[1], w1[1]), K2 = pk2(w1[2], w1[2]);
            const u64 K3 = pk2(w1[3], w1[3]), K4 = pk2(w1[4], w1[4]), K5 = pk2(w1[5], w1[5]);
            const u64 K6 = pk2(w1[6], w1[6]), K7 = pk2(w1[7], w1[7]), K8 = pk2(w1[8], w1[8]);
            const float b1v = eb1[e * DIM + c];
            const u64 B1 = pk2(b1v, b1v);

            u64 s[3];
#pragma unroll
            for (int ri = 0; ri < NIN; ri++) {
                P3 X = load3(in2 + ri * INW2, t);
                if (ri >= 2) {          // finish c1 row (ri-2) and store as fp16x2
                    u64 v = fma2(K6, X.p0, fma2(K7, X.p1, fma2(K8, X.p2, s[(ri - 2) % 3])));
                    float v0, v1; upk2(v, v0, v1);
                    const int hr = h0 + (ri - 2) - 1;
                    const bool hok = (unsigned)hr < (unsigned)HH;
                    // conv2's zero padding lives in the conv1-output domain
                    float r0 = hok ? fmaxf(v0, 0.f) : 0.f;
                    float r1 = hok ? fmaxf(v1, 0.f) : 0.f;
                    c1h[(ri - 2) * C1PW + t + 1] = __floats2half2_rn(r0, r1);
                }
                if (ri >= 1 && ri <= NC1)      // middle taps of c1 row (ri-1)
                    s[(ri - 1) % 3] = fma2(K3, X.p0, fma2(K4, X.p1, fma2(K5, X.p2, s[(ri - 1) % 3])));
                if (ri <= NC1 - 1)             // start c1 row ri
                    s[ri % 3] = fma2(K0, X.p0, fma2(K1, X.p1, fma2(K2, X.p2, B1)));
            }
        }
        __syncthreads();

        // ---- conv2 (scatter into acc[TR], weights pre-scaled by cof) ----
        {
            const u64 S0 = pk2(cof * w2[0], cof * w2[0]), S1 = pk2(cof * w2[1], cof * w2[1]);
            const u64 S2 = pk2(cof * w2[2], cof * w2[2]), S3 = pk2(cof * w2[3], cof * w2[3]);
            const u64 S4 = pk2(cof * w2[4], cof * w2[4]), S5 = pk2(cof * w2[5], cof * w2[5]);
            const u64 S6 = pk2(cof * w2[6], cof * w2[6]), S7 = pk2(cof * w2[7], cof * w2[7]);
            const u64 S8 = pk2(cof * w2[8], cof * w2[8]);
            const float bbv = cof * eb2[e * DIM + c];
            const u64 BB = pk2(bbv, bbv);

#pragma unroll
            for (int rr = 0; rr < NC1; rr++) {
                // pairs: idx t = cols(2t-2,2t-1), t+1 = (2t,2t+1), t+2 = (2t+2,2t+3)
                __half2 A = c1h[rr * C1PW + t];
                __half2 Bp = c1h[rr * C1PW + t + 1];
                __half2 Cp = c1h[rr * C1PW + t + 2];
                float fb = __high2float(A);    // col 2t-1
                float fc = __low2float(Bp);    // col 2t
                float fd = __high2float(Bp);   // col 2t+1
                float fe = __low2float(Cp);    // col 2t+2
                u64 p0 = pk2(fb, fc);
                u64 p1 = pk2(fc, fd);
                u64 p2 = pk2(fd, fe);
                if (rr <= TR - 1)
                    acc[rr]     = fma2(S0, p0, fma2(S1, p1, fma2(S2, p2, acc[rr])));
                if (rr >= 1 && rr <= TR)
                    acc[rr - 1] = fma2(S3, p0, fma2(S4, p1, fma2(S5, p2, acc[rr - 1])));
                if (rr >= 2)
                    acc[rr - 2] = fma2(S6, p0, fma2(S7, p1, fma2(S8, p2, acc[rr - 2])));
            }
#pragma unroll
            for (int o = 0; o < TR; o++) acc[o] = add2(acc[o], BB);
        }
        __syncthreads();
    }

    float* op = out + (size_t)(b * DIM + c) * (HH * WW) + h0 * WW + 2 * t;
#pragma unroll
    for (int r = 0; r < TR; r++) {
        float o0, o1; upk2(acc[r], o0, o1);
        reinterpret_cast<float2*>(op + r * WW)[0] = make_float2(o0, o1);
    }
}

// ---------------------------------------------------------------
extern "C" void kernel_launch(void* const* d_in, const int* in_sizes, int n_in,
                              void* d_out, int out_size) {
    const float* x     = (const float*)d_in[0];
    const float* w_fc0 = (const float*)d_in[1];
    const float* b_fc0 = (const float*)d_in[2];
    const float* w_fc1 = (const float*)d_in[3];
    const float* b_fc1 = (const float*)d_in[4];
    const float* ew1   = (const float*)d_in[5];
    const float* eb1   = (const float*)d_in[6];
    const float* ew2   = (const float*)d_in[7];
    const float* eb2   = (const float*)d_in[8];
    float* out = (float*)d_out;

    pool_gate_kernel<<<BATCH * DIM, 256>>>(x, w_fc0, b_fc0, w_fc1, b_fc1);
    dim3 grid(HH / TR, DIM, BATCH);
    moe_kernel<<<grid, 96>>>(x, ew1, eb1, ew2, eb2, out);
}

// round 14
// speedup vs baseline: 1.6142x; 1.0673x over previous
#include <cuda_runtime.h>
#include <cuda_bf16.h>
#include <cuda_fp16.h>
#include <math.h>

#define BATCH 8
#define DIM 96
#define HH 192
#define WW 192
#define NEXP 6
#define TOPK 3

#define TR 12             // output rows per tile
#define NIN (TR + 4)      // input rows per tile (16)
#define NC1 (TR + 2)      // conv1 rows per tile (14)

typedef unsigned long long u64;

// ---------- packed f32x2 helpers (sm_103a) ----------
__device__ __forceinline__ u64 pk2(float lo, float hi) {
    u64 d; asm("mov.b64 %0, {%1, %2};" : "=l"(d) : "f"(lo), "f"(hi)); return d;
}
__device__ __forceinline__ void upk2(u64 d, float& lo, float& hi) {
    asm("mov.b64 {%0, %1}, %2;" : "=f"(lo), "=f"(hi) : "l"(d));
}
__device__ __forceinline__ u64 fma2(u64 a, u64 b, u64 c) {
    u64 d; asm("fma.rn.f32x2 %0, %1, %2, %3;" : "=l"(d) : "l"(a), "l"(b), "l"(c)); return d;
}
__device__ __forceinline__ u64 add2(u64 a, u64 b) {
    u64 d; asm("add.rn.f32x2 %0, %1, %2;" : "=l"(d) : "l"(a), "l"(b)); return d;
}

// ---------- device scratch ----------
__device__ float g_pooled[BATCH * DIM];
__device__ int   g_idx[BATCH * TOPK];
__device__ float g_w[BATCH * TOPK];
__device__ unsigned int g_done = 0;   // self-resetting completion counter

// ---------------------------------------------------------------
// Kernel A: fused pooling + gate (last-block pattern, self-resetting).
// ---------------------------------------------------------------
__global__ __launch_bounds__(256) void pool_gate_kernel(
    const float* __restrict__ x,
    const float* __restrict__ w_fc0, const float* __restrict__ b_fc0,
    const float* __restrict__ w_fc1, const float* __restrict__ b_fc1)
{
    __shared__ float smx[8], ssm[8];
    __shared__ int   s_last;
    __shared__ float sh_g[BATCH][NEXP], sh_nz[BATCH][NEXP];

    const int bc = blockIdx.x;
    const int tid = threadIdx.x;
    const float4* p4 = reinterpret_cast<const float4*>(x + (size_t)bc * (HH * WW));
    float mx = -1e30f, sm = 0.f;
    for (int i = tid; i < (HH * WW / 4); i += 256) {
        float4 v = p4[i];
        mx = fmaxf(mx, fmaxf(fmaxf(v.x, v.y), fmaxf(v.z, v.w)));
        sm += (v.x + v.y) + (v.z + v.w);
    }
#pragma unroll
    for (int o = 16; o; o >>= 1) {
        mx = fmaxf(mx, __shfl_xor_sync(0xffffffffu, mx, o));
        sm += __shfl_xor_sync(0xffffffffu, sm, o);
    }
    int w = tid >> 5, l = tid & 31;
    if (l == 0) { smx[w] = mx; ssm[w] = sm; }
    __syncthreads();
    if (tid == 0) {
        float M = smx[0], S = ssm[0];
#pragma unroll
        for (int i = 1; i < 8; i++) { M = fmaxf(M, smx[i]); S += ssm[i]; }
        g_pooled[bc] = M + S * (1.0f / (HH * WW));
        __threadfence();                                   // release g_pooled
        unsigned int old = atomicAdd(&g_done, 1u);
        s_last = (old == (unsigned)(BATCH * DIM - 1)) ? 1 : 0;
    }
    __syncthreads();
    if (!s_last) return;

    // ---- last block: gate ----
    __threadfence();                                       // acquire g_pooled
    if (tid == 0) g_done = 0;                              // reset for replay
    if (tid < BATCH * NEXP) {
        int b = tid / NEXP, e = tid - b * NEXP;
        const float* p = g_pooled + b * DIM;
        float d0 = b_fc0[e], d1 = b_fc1[e];
        for (int c = 0; c < DIM; c++) {
            float pv = p[c];
            d0 = fmaf(pv, w_fc0[e * DIM + c], d0);
            d1 = fmaf(pv, w_fc1[e * DIM + c], d1);
        }
        sh_g[b][e]  = (d1 >= 0.f) ? d1 : 0.2f * d1;                  // leaky_relu 0.2
        sh_nz[b][e] = fmaxf(d0, 0.f) + log1pf(expf(-fabsf(d0)));     // stable softplus
    }
    __syncthreads();
    if (tid < BATCH) {
        int b = tid;
        float g[NEXP], nz[NEXP];
#pragma unroll
        for (int e = 0; e < NEXP; e++) { g[e] = sh_g[b][e]; nz[e] = sh_nz[b][e]; }
        float mu = 0.f;
#pragma unroll
        for (int e = 0; e < NEXP; e++) mu += nz[e];
        mu *= (1.0f / NEXP);
        float var = 0.f;
#pragma unroll
        for (int e = 0; e < NEXP; e++) { float d = nz[e] - mu; var += d * d; }
        float sd = sqrtf(var / (NEXP - 1));                          // ddof=1
        float sc[NEXP];
#pragma unroll
        for (int e = 0; e < NEXP; e++) sc[e] = g[e] + (nz[e] - mu) / sd;

        bool used[NEXP] = {false, false, false, false, false, false};
        int idx[TOPK];
#pragma unroll
        for (int k = 0; k < TOPK; k++) {
            float best = -1e30f; int bi = 0;
#pragma unroll
            for (int e = 0; e < NEXP; e++)
                if (!used[e] && sc[e] > best) { best = sc[e]; bi = e; }
            used[bi] = true;
            idx[k] = bi;
        }
        float m = fmaxf(g[idx[0]], fmaxf(g[idx[1]], g[idx[2]]));
        float ex[TOPK], s = 0.f;
#pragma unroll
        for (int k = 0; k < TOPK; k++) { ex[k] = expf(g[idx[k]] - m); s += ex[k]; }
        float inv = 1.0f / s;
#pragma unroll
        for (int k = 0; k < TOPK; k++) {
            g_idx[b * TOPK + k] = idx[k];
            g_w[b * TOPK + k]   = ex[k] * inv;
        }
    }
}

// ---------------------------------------------------------------
// Kernel C: fused conv1 -> relu -> conv2 -> weighted sum (f32x2).
// Scatter form, 12-row tiles, fp16x2 c1. EDGE template: only the first
// and last row-tile pay the per-row image-boundary masking.
// ---------------------------------------------------------------
#define INW 196
#define INW2 98
#define C1PW 100   // u32 pairs per c1 row

struct P3 { u64 p0, p1, p2; };

__device__ __forceinline__ P3 load3(const float2* row, int t) {
    float2 L = row[t];       // cols (2t-1, 2t)
    float2 R = row[t + 1];   // cols (2t+1, 2t+2)
    P3 r;
    r.p0 = pk2(L.x, L.y);
    r.p1 = pk2(L.y, R.x);
    r.p2 = pk2(R.x, R.y);
    return r;
}

template <bool EDGE>
__device__ __forceinline__ void run_experts(
    const float2* in2, __half2* c1h, u64* acc, int t, int h0, int b, int c,
    const float* __restrict__ ew1, const float* __restrict__ eb1,
    const float* __restrict__ ew2, const float* __restrict__ eb2)
{
    for (int ki = 0; ki < TOPK; ki++) {
        const int   e   = g_idx[b * TOPK + ki];
        const float cof = g_w[b * TOPK + ki];
        const float* w1 = ew1 + ((size_t)e * DIM + c) * 9;
        const float* w2 = ew2 + ((size_t)e * DIM + c) * 9;

        // ---- conv1 + relu -> c1h (scatter, 3-slot circular accumulator) ----
        {
            const u64 K0 = pk2(w1[0], w1[0]), K1 = pk2(w1[1], w1[1]), K2 = pk2(w1[2], w1[2]);
            const u64 K3 = pk2(w1[3], w1[3]), K4 = pk2(w1[4], w1[4]), K5 = pk2(w1[5], w1[5]);
            const u64 K6 = pk2(w1[6], w1[6]), K7 = pk2(w1[7], w1[7]), K8 = pk2(w1[8], w1[8]);
            const float b1v = eb1[e * DIM + c];
            const u64 B1 = pk2(b1v, b1v);

            u64 s[3];
#pragma unroll
            for (int ri = 0; ri < NIN; ri++) {
                P3 X = load3(in2 + ri * INW2, t);
                if (ri >= 2) {          // finish c1 row (ri-2), store as fp16x2
                    u64 v = fma2(K6, X.p0, fma2(K7, X.p1, fma2(K8, X.p2, s[(ri - 2) % 3])));
                    float v0, v1; upk2(v, v0, v1);
                    float r0 = fmaxf(v0, 0.f), r1 = fmaxf(v1, 0.f);
                    if (EDGE) {
                        const int hr = h0 + (ri - 2) - 1;
                        const bool hok = (unsigned)hr < (unsigned)HH;
                        // conv2's zero padding lives in the conv1-output domain
                        r0 = hok ? r0 : 0.f;
                        r1 = hok ? r1 : 0.f;
                    }
                    c1h[(ri - 2) * C1PW + t + 1] = __floats2half2_rn(r0, r1);
                }
                if (ri >= 1 && ri <= NC1)      // middle taps of c1 row (ri-1)
                    s[(ri - 1) % 3] = fma2(K3, X.p0, fma2(K4, X.p1, fma2(K5, X.p2, s[(ri - 1) % 3])));
                if (ri <= NC1 - 1)             // start c1 row ri
                    s[ri % 3] = fma2(K0, X.p0, fma2(K1, X.p1, fma2(K2, X.p2, B1)));
            }
        }
        __syncthreads();

        // ---- conv2 (scatter into acc[TR], weights pre-scaled by cof) ----
        {
            const u64 S0 = pk2(cof * w2[0], cof * w2[0]), S1 = pk2(cof * w2[1], cof * w2[1]);
            const u64 S2 = pk2(cof * w2[2], cof * w2[2]), S3 = pk2(cof * w2[3], cof * w2[3]);
            const u64 S4 = pk2(cof * w2[4], cof * w2[4]), S5 = pk2(cof * w2[5], cof * w2[5]);
            const u64 S6 = pk2(cof * w2[6], cof * w2[6]), S7 = pk2(cof * w2[7], cof * w2[7]);
            const u64 S8 = pk2(cof * w2[8], cof * w2[8]);
            const float bbv = cof * eb2[e * DIM + c];
            const u64 BB = pk2(bbv, bbv);

#pragma unroll
            for (int rr = 0; rr < NC1; rr++) {
                __half2 A  = c1h[rr * C1PW + t];
                __half2 Bp = c1h[rr * C1PW + t + 1];
                __half2 Cp = c1h[rr * C1PW + t + 2];
                float fb = __high2float(A);    // col 2t-1
                float fc = __low2float(Bp);    // col 2t
                float fd = __high2float(Bp);   // col 2t+1
                float fe = __low2float(Cp);    // col 2t+2
                u64 p0 = pk2(fb, fc);
                u64 p1 = pk2(fc, fd);
                u64 p2 = pk2(fd, fe);
                if (rr <= TR - 1)
                    acc[rr]     = fma2(S0, p0, fma2(S1, p1, fma2(S2, p2, acc[rr])));
                if (rr >= 1 && rr <= TR)
                    acc[rr - 1] = fma2(S3, p0, fma2(S4, p1, fma2(S5, p2, acc[rr - 1])));
                if (rr >= 2)
                    acc[rr - 2] = fma2(S6, p0, fma2(S7, p1, fma2(S8, p2, acc[rr - 2])));
            }
#pragma unroll
            for (int o = 0; o < TR; o++) acc[o] = add2(acc[o], BB);
        }
        __syncthreads();
    }
}

__global__ __launch_bounds__(96) void moe_kernel(
    const float* __restrict__ x,
    const float* __restrict__ ew1, const float* __restrict__ eb1,
    const float* __restrict__ ew2, const float* __restrict__ eb2,
    float* __restrict__ out)
{
    const int t  = threadIdx.x;             // 0..95, column pair (2t, 2t+1)
    const int h0 = blockIdx.x * TR;
    const int c  = blockIdx.y;
    const int b  = blockIdx.z;
    const bool vedge = (blockIdx.x == 0) || (blockIdx.x == (HH / TR - 1));

    // x tile: rows h0-2..h0+TR+1 (NIN), col j at idx j+1; idx 0 & 193 zero pad
    __shared__ __align__(16) float in_s[NIN * INW];
    // relu(conv1) as fp16x2 pairs: rows h0-1..h0+TR (NC1)
    __shared__ __half2 c1h[NC1 * C1PW];

    // ---- vectorized tile load: NIN row passes, 1 coalesced float2 each ----
    const float* xp = x + (size_t)(b * DIM + c) * (HH * WW);
#pragma unroll 4
    for (int ri = 0; ri < NIN; ri++) {
        const int h = h0 - 2 + ri;
        float2 v = make_float2(0.f, 0.f);
        if ((unsigned)h < (unsigned)HH)
            v = reinterpret_cast<const float2*>(xp + h * WW)[t];
        in_s[ri * INW + 2 * t + 1] = v.x;
        in_s[ri * INW + 2 * t + 2] = v.y;
        if (t == 0) { in_s[ri * INW + 0] = 0.f; in_s[ri * INW + 193] = 0.f; }
    }
    // c1 halo pairs: idx 0 = cols(-2,-1), idx 97 = cols(192,193): always zero
    if (t < NC1) {
        c1h[t * C1PW + 0]  = __floats2half2_rn(0.f, 0.f);
        c1h[t * C1PW + 97] = __floats2half2_rn(0.f, 0.f);
    }

    u64 acc[TR];
#pragma unroll
    for (int r = 0; r < TR; r++) acc[r] = 0ull;
    __syncthreads();

    const float2* in2 = reinterpret_cast<const float2*>(in_s);
    if (vedge)
        run_experts<true >(in2, c1h, acc, t, h0, b, c, ew1, eb1, ew2, eb2);
    else
        run_experts<false>(in2, c1h, acc, t, h0, b, c, ew1, eb1, ew2, eb2);

    float* op = out + (size_t)(b * DIM + c) * (HH * WW) + h0 * WW + 2 * t;
#pragma unroll
    for (int r = 0; r < TR; r++) {
        float o0, o1; upk2(acc[r], o0, o1);
        reinterpret_cast<float2*>(op + r * WW)[0] = make_float2(o0, o1);
    }
}

// ---------------------------------------------------------------
extern "C" void kernel_launch(void* const* d_in, const int* in_sizes, int n_in,
                              void* d_out, int out_size) {
    const float* x     = (const float*)d_in[0];
    const float* w_fc0 = (const float*)d_in[1];
    const float* b_fc0 = (const float*)d_in[2];
    const float* w_fc1 = (const float*)d_in[3];
    const float* b_fc1 = (const float*)d_in[4];
    const float* ew1   = (const float*)d_in[5];
    const float* eb1   = (const float*)d_in[6];
    const float* ew2   = (const float*)d_in[7];
    const float* eb2   = (const float*)d_in[8];
    float* out = (float*)d_out;

    pool_gate_kernel<<<BATCH * DIM, 256>>>(x, w_fc0, b_fc0, w_fc1, b_fc1);
    dim3 grid(HH / TR, DIM, BATCH);
    moe_kernel<<<grid, 96>>>(x, ew1, eb1, ew2, eb2, out);
}